// round 1
// baseline (speedup 1.0000x reference)
#include <cuda_runtime.h>
#include <math.h>

// Problem constants
#define B_  32
#define C_  512
#define M_  784            // 28*28
#define NSQ (C_*C_)        // 262144
#define TOT ((long)B_*NSQ)

// ---------------- scratch (static device globals; no allocation) ----------------
__device__ float g_A [B_*NSQ];   // cov -> An -> Y ping buffer 0
__device__ float g_Yb[B_*NSQ];   // Y ping buffer 1 (also final Ysqrt)
__device__ float g_Z0[B_*NSQ];
__device__ float g_Z1[B_*NSQ];
__device__ float g_W [B_*NSQ];   // W = 1.5 I - 0.5 Z@Y
__device__ float g_mean[B_*C_];
__device__ float g_itr[B_];      // 1/trace
__device__ float g_str[B_];      // sqrt(trace)
__device__ float g_cs [B_*C_];   // cov_sum (column means * sqrt(trace))

// ---------------- per-row mean of x (one warp per (b,c) row) ----------------
__global__ void mean_kernel(const float* __restrict__ x, float* __restrict__ mean)
{
    int warp = (blockIdx.x * blockDim.x + threadIdx.x) >> 5;
    int lane = threadIdx.x & 31;
    if (warp >= B_*C_) return;
    const float* row = x + (long)warp * M_;
    float s = 0.f;
    for (int k = lane; k < M_; k += 32) s += row[k];
    #pragma unroll
    for (int off = 16; off; off >>= 1) s += __shfl_down_sync(0xffffffffu, s, off);
    if (lane == 0) mean[warp] = s * (1.0f / M_);
}

// ---------------- batched SGEMM: 128x128x8 tile, 256 threads, 8x8/thread ----------------
// MODE 0: C = acc                  (plain product)
// MODE 1: C = 1.5*(i==j) - 0.5*acc (Newton-Schulz W)
// MODE 2: C = acc*covInvM - mean[i]*mean[j]   (covariance epilogue)
// BT: B operand given as [N,K] row-major (use B^T), i.e. load like A.
template<int MODE, bool BT>
__global__ void __launch_bounds__(256)
gemm_kernel(const float* __restrict__ Ag, const float* __restrict__ Bg,
            float* __restrict__ Cg,
            int K, int lda, int ldb, int ldc,
            long strideA, long strideB, long strideC,
            const float* __restrict__ meang, float covInvM)
{
    __shared__ float As[8][128];
    __shared__ float Bs[8][128];

    const int b = blockIdx.z;
    const float* A  = Ag + (long)b * strideA;
    const float* Bp = Bg + (long)b * strideB;
    float*       C  = Cg + (long)b * strideC;

    const int ib = blockIdx.y * 128;
    const int jb = blockIdx.x * 128;
    const int tid = threadIdx.x;
    const int tx = tid & 15;
    const int ty = tid >> 4;

    float acc[8][8];
    #pragma unroll
    for (int i = 0; i < 8; i++)
        #pragma unroll
        for (int j = 0; j < 8; j++) acc[i][j] = 0.f;

    // A tile loader indices: 128 rows x 8 cols, one float4 per thread
    const int arow = tid >> 1;
    const int acol = (tid & 1) * 4;
    // B tile loader indices
    const int brow = BT ? (tid >> 1) : (tid >> 5);
    const int bcol = BT ? ((tid & 1) * 4) : ((tid & 31) * 4);

    for (int k0 = 0; k0 < K; k0 += 8) {
        float4 av = *(const float4*)(A + (long)(ib + arow) * lda + k0 + acol);
        As[acol + 0][arow] = av.x;
        As[acol + 1][arow] = av.y;
        As[acol + 2][arow] = av.z;
        As[acol + 3][arow] = av.w;
        if (BT) {
            float4 bv = *(const float4*)(Bp + (long)(jb + brow) * ldb + k0 + bcol);
            Bs[bcol + 0][brow] = bv.x;
            Bs[bcol + 1][brow] = bv.y;
            Bs[bcol + 2][brow] = bv.z;
            Bs[bcol + 3][brow] = bv.w;
        } else {
            *(float4*)(&Bs[brow][bcol]) =
                *(const float4*)(Bp + (long)(k0 + brow) * ldb + jb + bcol);
        }
        __syncthreads();

        #pragma unroll
        for (int kk = 0; kk < 8; kk++) {
            float a[8], bb[8];
            *(float4*)(a)      = *(const float4*)(&As[kk][ty * 8]);
            *(float4*)(a + 4)  = *(const float4*)(&As[kk][ty * 8 + 4]);
            *(float4*)(bb)     = *(const float4*)(&Bs[kk][tx * 8]);
            *(float4*)(bb + 4) = *(const float4*)(&Bs[kk][tx * 8 + 4]);
            #pragma unroll
            for (int i = 0; i < 8; i++)
                #pragma unroll
                for (int j = 0; j < 8; j++)
                    acc[i][j] = fmaf(a[i], bb[j], acc[i][j]);
        }
        __syncthreads();
    }

    // epilogue
    #pragma unroll
    for (int i = 0; i < 8; i++) {
        const int gi = ib + ty * 8 + i;
        float mi = 0.f;
        if (MODE == 2) mi = meang[b * C_ + gi];
        #pragma unroll
        for (int j = 0; j < 8; j += 4) {
            const int gj = jb + tx * 8 + j;
            float4 v;
            float* vv = (float*)&v;
            #pragma unroll
            for (int q = 0; q < 4; q++) {
                float r = acc[i][j + q];
                if (MODE == 1)      r = (gi == gj + q ? 1.5f : 0.0f) - 0.5f * r;
                else if (MODE == 2) r = r * covInvM - mi * meang[b * C_ + gj + q];
                vv[q] = r;
            }
            *(float4*)(C + (long)gi * ldc + gj) = v;
        }
    }
}

// ---------------- trace of A per batch ----------------
__global__ void trace_kernel(const float* __restrict__ A,
                             float* __restrict__ itr, float* __restrict__ str)
{
    __shared__ float sh[512];
    const int b = blockIdx.x;
    const int i = threadIdx.x;
    sh[i] = A[(long)b * NSQ + (long)i * C_ + i];
    __syncthreads();
    for (int off = 256; off; off >>= 1) {
        if (i < off) sh[i] += sh[i + off];
        __syncthreads();
    }
    if (i == 0) {
        float t = sh[0];
        itr[b] = 1.0f / t;
        str[b] = sqrtf(t);
    }
}

// ---------------- Y = A/trace (in place), Z = I ----------------
__global__ void init_kernel(float* __restrict__ A, float* __restrict__ Z,
                            const float* __restrict__ itr)
{
    long idx = (long)blockIdx.x * blockDim.x + threadIdx.x;   // float4 index
    if (idx >= TOT / 4) return;
    long e = idx * 4;
    int  b = (int)(e / NSQ);
    long r = e % NSQ;
    int  i = (int)(r / C_);
    int  j = (int)(r % C_);
    float s = itr[b];
    float4 a = *(float4*)(A + e);
    a.x *= s; a.y *= s; a.z *= s; a.w *= s;
    *(float4*)(A + e) = a;
    float4 z = make_float4(0.f, 0.f, 0.f, 0.f);
    if (i >= j && i < j + 4) ((float*)&z)[i - j] = 1.0f;
    *(float4*)(Z + e) = z;
}

// ---------------- cov_sum[b][j] = sqrt(trace)/C * sum_i Ysqrt[b][i][j] ----------------
__global__ void colmean_kernel(const float* __restrict__ Y,
                               const float* __restrict__ str,
                               float* __restrict__ cs)
{
    const int b = blockIdx.x;
    const int j = threadIdx.x;
    const float* base = Y + (long)b * NSQ + j;
    float s = 0.f;
    #pragma unroll 8
    for (int i = 0; i < C_; i++) s += base[(long)i * C_];
    cs[b * C_ + j] = s * str[b] * (1.0f / C_);
}

// ---------------- out = cov_sum[b][c] * x ----------------
__global__ void scale_kernel(const float* __restrict__ x,
                             const float* __restrict__ cs,
                             float* __restrict__ out)
{
    long i4 = (long)blockIdx.x * blockDim.x + threadIdx.x;
    const long total4 = (long)B_ * C_ * M_ / 4;
    if (i4 >= total4) return;
    long e = i4 * 4;
    int bc = (int)(e / M_);       // M_ % 4 == 0, so one float4 stays in one row
    float s = cs[bc];
    float4 v = *(const float4*)(x + e);
    v.x *= s; v.y *= s; v.z *= s; v.w *= s;
    *(float4*)(out + e) = v;
}

// ---------------- launcher ----------------
extern "C" void kernel_launch(void* const* d_in, const int* in_sizes, int n_in,
                              void* d_out, int out_size)
{
    const float* x = (const float*)d_in[0];
    float* out = (float*)d_out;

    float *A, *Yb, *Z0, *Z1, *W, *mean, *itr, *str, *cs;
    cudaGetSymbolAddress((void**)&A,    g_A);
    cudaGetSymbolAddress((void**)&Yb,   g_Yb);
    cudaGetSymbolAddress((void**)&Z0,   g_Z0);
    cudaGetSymbolAddress((void**)&Z1,   g_Z1);
    cudaGetSymbolAddress((void**)&W,    g_W);
    cudaGetSymbolAddress((void**)&mean, g_mean);
    cudaGetSymbolAddress((void**)&itr,  g_itr);
    cudaGetSymbolAddress((void**)&str,  g_str);
    cudaGetSymbolAddress((void**)&cs,   g_cs);

    const dim3 gemm_grid(4, 4, B_);   // 128x128 tiles over 512x512, 32 batches
    const long sX = (long)C_ * M_;

    // 1) means
    mean_kernel<<<(B_*C_ + 7) / 8, 256>>>(x, mean);

    // 2) cov = (x x^T)/M - mean (x) mean   (x is [C,M] per batch; B operand = x^T)
    gemm_kernel<2, true><<<gemm_grid, 256>>>(x, x, A,
        M_, M_, M_, C_, sX, sX, (long)NSQ, mean, 1.0f / M_);

    // 3) trace, 1/trace, sqrt(trace)
    trace_kernel<<<B_, 512>>>(A, itr, str);

    // 4) Y = cov/trace (in place in A), Z = I
    init_kernel<<<(int)((TOT / 4 + 255) / 256), 256>>>(A, Z0, itr);

    // 5) Newton-Schulz: 4 iterations of {W = 1.5I - 0.5 Z@Y; Y = Y@W; Z = W@Z}
    float* Ycur = A;  float* Ynext = Yb;
    float* Zcur = Z0; float* Znext = Z1;
    for (int it = 0; it < 4; it++) {
        gemm_kernel<1, false><<<gemm_grid, 256>>>(Zcur, Ycur, W,
            C_, C_, C_, C_, (long)NSQ, (long)NSQ, (long)NSQ, nullptr, 0.f);
        gemm_kernel<0, false><<<gemm_grid, 256>>>(Ycur, W, Ynext,
            C_, C_, C_, C_, (long)NSQ, (long)NSQ, (long)NSQ, nullptr, 0.f);
        gemm_kernel<0, false><<<gemm_grid, 256>>>(W, Zcur, Znext,
            C_, C_, C_, C_, (long)NSQ, (long)NSQ, (long)NSQ, nullptr, 0.f);
        float* t;
        t = Ycur; Ycur = Ynext; Ynext = t;
        t = Zcur; Zcur = Znext; Znext = t;
    }

    // 6) final: W = 1.5I - 0.5 Z@Y; Ysqrt = Y@W  (into Ynext buffer)
    gemm_kernel<1, false><<<gemm_grid, 256>>>(Zcur, Ycur, W,
        C_, C_, C_, C_, (long)NSQ, (long)NSQ, (long)NSQ, nullptr, 0.f);
    gemm_kernel<0, false><<<gemm_grid, 256>>>(Ycur, W, Ynext,
        C_, C_, C_, C_, (long)NSQ, (long)NSQ, (long)NSQ, nullptr, 0.f);

    // 7) column means scaled by sqrt(trace)
    colmean_kernel<<<B_, C_>>>(Ynext, str, cs);

    // 8) out = cov_sum[b][c] * x
    const long total4 = (long)B_ * C_ * M_ / 4;
    scale_kernel<<<(int)((total4 + 255) / 256), 256>>>(x, cs, out);

    (void)in_sizes; (void)n_in; (void)out_size;
}

// round 3
// speedup vs baseline: 1.5718x; 1.5718x over previous
#include <cuda_runtime.h>
#include <math.h>
#include <stdint.h>

// Problem constants
#define B_  32
#define C_  512
#define M_  784            // 28*28
#define NSQ (C_*C_)        // 262144
#define TOT ((long)B_*NSQ)

// ---------------- scratch (static device globals; no allocation) ----------------
__device__ float g_A [B_*NSQ];
__device__ float g_Yb[B_*NSQ];
__device__ float g_Z0[B_*NSQ];
__device__ float g_Z1[B_*NSQ];
__device__ float g_W [B_*NSQ];
__device__ float g_mean[B_*C_];
__device__ float g_itr[B_];
__device__ float g_str[B_];
__device__ float g_cs [B_*C_];

// ================= warp-level tf32 MMA (sm_80 ISA, valid on sm_103 plain) =================
__device__ __forceinline__ void mma_tf32(float* c, const uint32_t* a, const uint32_t* b) {
    asm volatile("mma.sync.aligned.m16n8k8.row.col.f32.tf32.tf32.f32 "
        "{%0,%1,%2,%3}, {%4,%5,%6,%7}, {%8,%9}, {%0,%1,%2,%3};"
        : "+f"(c[0]), "+f"(c[1]), "+f"(c[2]), "+f"(c[3])
        : "r"(a[0]), "r"(a[1]), "r"(a[2]), "r"(a[3]), "r"(b[0]), "r"(b[1]));
}
#define HI_MASK 0xFFFFE000u
__device__ __forceinline__ void split_tf32(float x, uint32_t& hi, uint32_t& lo) {
    uint32_t xb = __float_as_uint(x);
    hi = xb & HI_MASK;
    float lof = x - __uint_as_float(hi);
    lo = __float_as_uint(lof) & HI_MASK;
}

// ================= tensor-core GEMM via mma.sync =================
// D[m,n] = sum_k A[m,k] * B[n,k]  (both K-major row-major) via 3xTF32.
// MODE 0: C = acc ; MODE 1: C = 1.5*(i==j) - 0.5*acc ; MODE 2: C = acc*covInvM - mean_i*mean_j
#define TILE 128
#define KCH  32
#define GT   256
#define APAD 36               // fp32 columns per smem row (padded)
#define ATILE_F (128*APAD)    // floats per operand tile
#define STAGE_F (2*ATILE_F)   // A + B
#define GEMM_SMEM (2*STAGE_F*4)   // 73728 bytes, double buffered

template<int MODE>
__global__ void __launch_bounds__(GT)
gemm_tc(const float* __restrict__ Ag, const float* __restrict__ Bg,
        float* __restrict__ Cg, int K, int lda, int ldb, int ldc,
        long sA, long sB, long sC, const float* __restrict__ meang, float covInvM)
{
    extern __shared__ float sm[];
    const int tid = threadIdx.x;
    const int b = blockIdx.z;
    const float* A  = Ag + (long)b * sA;
    const float* Bp = Bg + (long)b * sB;
    float*       C  = Cg + (long)b * sC;
    const int ib = blockIdx.y * TILE;
    const int jb = blockIdx.x * TILE;

    const int wid = tid >> 5, lane = tid & 31;
    const int wm = wid & 1, wn = wid >> 1;       // 2 x 4 warp grid: 64 rows x 32 cols each
    const int gid = lane >> 2, tig = lane & 3;

    float acc[4][4][4];
    #pragma unroll
    for (int mf = 0; mf < 4; mf++)
        #pragma unroll
        for (int nf = 0; nf < 4; nf++)
            #pragma unroll
            for (int e = 0; e < 4; e++) acc[mf][nf][e] = 0.f;

    const int NC = (K + KCH - 1) / KCH;

    // per-thread global load mapping: f = tid + q*256 ; row = f/8 ; col4 = (f%8)*4
    float4 ra[4], rb[4];

    // ---- preload chunk 0 ----
    #pragma unroll
    for (int q = 0; q < 4; q++) {
        int f = tid + q * GT; int r = f >> 3; int k = (f & 7) * 4;
        ra[q] = (k < K) ? *(const float4*)(A  + (long)(ib + r) * lda + k) : make_float4(0,0,0,0);
        rb[q] = (k < K) ? *(const float4*)(Bp + (long)(jb + r) * ldb + k) : make_float4(0,0,0,0);
    }
    // store to buffer 0
    #pragma unroll
    for (int q = 0; q < 4; q++) {
        int f = tid + q * GT; int r = f >> 3; int c = (f & 7) * 4;
        *(float4*)(sm + (long)r * APAD + c)           = ra[q];
        *(float4*)(sm + ATILE_F + (long)r * APAD + c) = rb[q];
    }
    __syncthreads();

    for (int i = 0; i < NC; i++) {
        // ---- preload next chunk into regs ----
        if (i + 1 < NC) {
            const int k0 = (i + 1) * KCH;
            #pragma unroll
            for (int q = 0; q < 4; q++) {
                int f = tid + q * GT; int r = f >> 3; int k = k0 + (f & 7) * 4;
                ra[q] = (k < K) ? *(const float4*)(A  + (long)(ib + r) * lda + k) : make_float4(0,0,0,0);
                rb[q] = (k < K) ? *(const float4*)(Bp + (long)(jb + r) * ldb + k) : make_float4(0,0,0,0);
            }
        }

        // ---- compute from buffer i&1 ----
        const float* As = sm + (i & 1) * STAGE_F;
        const float* Bs = As + ATILE_F;
        #pragma unroll
        for (int ks = 0; ks < 4; ks++) {
            uint32_t ah[4][4], al[4][4];
            #pragma unroll
            for (int mf = 0; mf < 4; mf++) {
                int base = (wm * 64 + mf * 16 + gid) * APAD + ks * 8 + tig;
                split_tf32(As[base],            ah[mf][0], al[mf][0]);
                split_tf32(As[base + 8 * APAD], ah[mf][1], al[mf][1]);
                split_tf32(As[base + 4],        ah[mf][2], al[mf][2]);
                split_tf32(As[base + 8 * APAD + 4], ah[mf][3], al[mf][3]);
            }
            uint32_t bh[4][2], bl[4][2];
            #pragma unroll
            for (int nf = 0; nf < 4; nf++) {
                int base = (wn * 32 + nf * 8 + gid) * APAD + ks * 8 + tig;
                split_tf32(Bs[base],     bh[nf][0], bl[nf][0]);
                split_tf32(Bs[base + 4], bh[nf][1], bl[nf][1]);
            }
            #pragma unroll
            for (int mf = 0; mf < 4; mf++)
                #pragma unroll
                for (int nf = 0; nf < 4; nf++) {
                    mma_tf32(acc[mf][nf], ah[mf], bh[nf]);
                    mma_tf32(acc[mf][nf], ah[mf], bl[nf]);
                    mma_tf32(acc[mf][nf], al[mf], bh[nf]);
                }
        }

        // ---- store next chunk to alternate buffer ----
        if (i + 1 < NC) {
            float* Ad = sm + ((i + 1) & 1) * STAGE_F;
            #pragma unroll
            for (int q = 0; q < 4; q++) {
                int f = tid + q * GT; int r = f >> 3; int c = (f & 7) * 4;
                *(float4*)(Ad + (long)r * APAD + c)           = ra[q];
                *(float4*)(Ad + ATILE_F + (long)r * APAD + c) = rb[q];
            }
        }
        __syncthreads();
    }

    // ---- epilogue ----
    #pragma unroll
    for (int mf = 0; mf < 4; mf++) {
        const int row0 = ib + wm * 64 + mf * 16 + gid;
        float mi0 = 0.f, mi1 = 0.f;
        if (MODE == 2) { mi0 = meang[b * C_ + row0]; mi1 = meang[b * C_ + row0 + 8]; }
        #pragma unroll
        for (int nf = 0; nf < 4; nf++) {
            const int col0 = jb + wn * 32 + nf * 8 + tig * 2;
            float c0 = acc[mf][nf][0], c1 = acc[mf][nf][1];
            float c2 = acc[mf][nf][2], c3 = acc[mf][nf][3];
            if (MODE == 1) {
                c0 = (row0 == col0     ? 1.5f : 0.f) - 0.5f * c0;
                c1 = (row0 == col0 + 1 ? 1.5f : 0.f) - 0.5f * c1;
                c2 = (row0 + 8 == col0     ? 1.5f : 0.f) - 0.5f * c2;
                c3 = (row0 + 8 == col0 + 1 ? 1.5f : 0.f) - 0.5f * c3;
            } else if (MODE == 2) {
                float mj0 = meang[b * C_ + col0], mj1 = meang[b * C_ + col0 + 1];
                c0 = c0 * covInvM - mi0 * mj0;
                c1 = c1 * covInvM - mi0 * mj1;
                c2 = c2 * covInvM - mi1 * mj0;
                c3 = c3 * covInvM - mi1 * mj1;
            }
            *(float2*)(C + (long)row0 * ldc + col0)       = make_float2(c0, c1);
            *(float2*)(C + (long)(row0 + 8) * ldc + col0) = make_float2(c2, c3);
        }
    }
}

// ---------------- per-row mean of x ----------------
__global__ void mean_kernel(const float* __restrict__ x, float* __restrict__ mean)
{
    int warp = (blockIdx.x * blockDim.x + threadIdx.x) >> 5;
    int lane = threadIdx.x & 31;
    if (warp >= B_*C_) return;
    const float* row = x + (long)warp * M_;
    float s = 0.f;
    for (int k = lane; k < M_; k += 32) s += row[k];
    #pragma unroll
    for (int off = 16; off; off >>= 1) s += __shfl_down_sync(0xffffffffu, s, off);
    if (lane == 0) mean[warp] = s * (1.0f / M_);
}

// ---------------- trace ----------------
__global__ void trace_kernel(const float* __restrict__ A,
                             float* __restrict__ itr, float* __restrict__ str)
{
    __shared__ float sh[512];
    const int b = blockIdx.x;
    const int i = threadIdx.x;
    sh[i] = A[(long)b * NSQ + (long)i * C_ + i];
    __syncthreads();
    for (int off = 256; off; off >>= 1) {
        if (i < off) sh[i] += sh[i + off];
        __syncthreads();
    }
    if (i == 0) { float t = sh[0]; itr[b] = 1.0f / t; str[b] = sqrtf(t); }
}

// ---------------- Y = A/trace, Z = I ----------------
__global__ void init_kernel(float* __restrict__ A, float* __restrict__ Z,
                            const float* __restrict__ itr)
{
    long idx = (long)blockIdx.x * blockDim.x + threadIdx.x;
    if (idx >= TOT / 4) return;
    long e = idx * 4;
    int  b = (int)(e / NSQ);
    long r = e % NSQ;
    int  i = (int)(r / C_);
    int  j = (int)(r % C_);
    float s = itr[b];
    float4 a = *(float4*)(A + e);
    a.x *= s; a.y *= s; a.z *= s; a.w *= s;
    *(float4*)(A + e) = a;
    float4 z = make_float4(0.f, 0.f, 0.f, 0.f);
    if (i >= j && i < j + 4) ((float*)&z)[i - j] = 1.0f;
    *(float4*)(Z + e) = z;
}

// ---------------- column mean ----------------
__global__ void colmean_kernel(const float* __restrict__ Y,
                               const float* __restrict__ str, float* __restrict__ cs)
{
    const int b = blockIdx.x;
    const int j = threadIdx.x;
    const float* base = Y + (long)b * NSQ + j;
    float s = 0.f;
    #pragma unroll 8
    for (int i = 0; i < C_; i++) s += base[(long)i * C_];
    cs[b * C_ + j] = s * str[b] * (1.0f / C_);
}

// ---------------- out = cov_sum * x ----------------
__global__ void scale_kernel(const float* __restrict__ x,
                             const float* __restrict__ cs, float* __restrict__ out)
{
    long i4 = (long)blockIdx.x * blockDim.x + threadIdx.x;
    const long total4 = (long)B_ * C_ * M_ / 4;
    if (i4 >= total4) return;
    long e = i4 * 4;
    int bc = (int)(e / M_);
    float s = cs[bc];
    float4 v = *(const float4*)(x + e);
    v.x *= s; v.y *= s; v.z *= s; v.w *= s;
    *(float4*)(out + e) = v;
}

// ---------------- launcher ----------------
extern "C" void kernel_launch(void* const* d_in, const int* in_sizes, int n_in,
                              void* d_out, int out_size)
{
    const float* x = (const float*)d_in[0];
    float* out = (float*)d_out;

    float *A, *Yb, *Z0, *Z1, *W, *mean, *itr, *str, *cs;
    cudaGetSymbolAddress((void**)&A,    g_A);
    cudaGetSymbolAddress((void**)&Yb,   g_Yb);
    cudaGetSymbolAddress((void**)&Z0,   g_Z0);
    cudaGetSymbolAddress((void**)&Z1,   g_Z1);
    cudaGetSymbolAddress((void**)&W,    g_W);
    cudaGetSymbolAddress((void**)&mean, g_mean);
    cudaGetSymbolAddress((void**)&itr,  g_itr);
    cudaGetSymbolAddress((void**)&str,  g_str);
    cudaGetSymbolAddress((void**)&cs,   g_cs);

    cudaFuncSetAttribute(gemm_tc<0>, cudaFuncAttributeMaxDynamicSharedMemorySize, GEMM_SMEM);
    cudaFuncSetAttribute(gemm_tc<1>, cudaFuncAttributeMaxDynamicSharedMemorySize, GEMM_SMEM);
    cudaFuncSetAttribute(gemm_tc<2>, cudaFuncAttributeMaxDynamicSharedMemorySize, GEMM_SMEM);

    const dim3 grid(4, 4, B_);   // N-tiles x M-tiles x batch
    const long sX = (long)C_ * M_;

    mean_kernel<<<(B_*C_ + 7) / 8, 256>>>(x, mean);

    // cov = (x x^T)/M - mean (x) mean    (A = B = x, K-major)
    gemm_tc<2><<<grid, GT, GEMM_SMEM>>>(x, x, A, M_, M_, M_, C_,
                                        sX, sX, (long)NSQ, mean, 1.0f / M_);

    trace_kernel<<<B_, 512>>>(A, itr, str);
    init_kernel<<<(int)((TOT / 4 + 255) / 256), 256>>>(A, Z0, itr);

    // Newton-Schulz (all operands symmetric -> A@B == A@B^T, K-major both sides)
    float* Ycur = A;  float* Ynext = Yb;
    float* Zcur = Z0; float* Znext = Z1;
    for (int it = 0; it < 4; it++) {
        gemm_tc<1><<<grid, GT, GEMM_SMEM>>>(Zcur, Ycur, W, C_, C_, C_, C_,
                                            (long)NSQ, (long)NSQ, (long)NSQ, nullptr, 0.f);
        gemm_tc<0><<<grid, GT, GEMM_SMEM>>>(Ycur, W, Ynext, C_, C_, C_, C_,
                                            (long)NSQ, (long)NSQ, (long)NSQ, nullptr, 0.f);
        gemm_tc<0><<<grid, GT, GEMM_SMEM>>>(W, Zcur, Znext, C_, C_, C_, C_,
                                            (long)NSQ, (long)NSQ, (long)NSQ, nullptr, 0.f);
        float* t;
        t = Ycur; Ycur = Ynext; Ynext = t;
        t = Zcur; Zcur = Znext; Znext = t;
    }
    gemm_tc<1><<<grid, GT, GEMM_SMEM>>>(Zcur, Ycur, W, C_, C_, C_, C_,
                                        (long)NSQ, (long)NSQ, (long)NSQ, nullptr, 0.f);
    gemm_tc<0><<<grid, GT, GEMM_SMEM>>>(Ycur, W, Ynext, C_, C_, C_, C_,
                                        (long)NSQ, (long)NSQ, (long)NSQ, nullptr, 0.f);

    colmean_kernel<<<B_, C_>>>(Ynext, str, cs);

    const long total4 = (long)B_ * C_ * M_ / 4;
    scale_kernel<<<(int)((total4 + 255) / 256), 256>>>(x, cs, out);

    (void)in_sizes; (void)n_in; (void)out_size;
}

// round 4
// speedup vs baseline: 2.8842x; 1.8350x over previous
#include <cuda_runtime.h>
#include <math.h>
#include <stdint.h>

// Problem constants
#define B_  32
#define C_  512
#define M_  784            // 28*28
#define NSQ (C_*C_)        // 262144

// ---------------- scratch ----------------
__device__ float g_A [B_*NSQ];   // covariance matrices
__device__ float g_mean[B_*C_];
__device__ float g_itr[B_];      // 1/trace
__device__ float g_str[B_];      // sqrt(trace)
__device__ float g_cs [B_*C_];   // final column means

// ================= warp-level tf32 MMA (sm_80 ISA) =================
__device__ __forceinline__ void mma_tf32(float* c, const uint32_t* a, const uint32_t* b) {
    asm volatile("mma.sync.aligned.m16n8k8.row.col.f32.tf32.tf32.f32 "
        "{%0,%1,%2,%3}, {%4,%5,%6,%7}, {%8,%9}, {%0,%1,%2,%3};"
        : "+f"(c[0]), "+f"(c[1]), "+f"(c[2]), "+f"(c[3])
        : "r"(a[0]), "r"(a[1]), "r"(a[2]), "r"(a[3]), "r"(b[0]), "r"(b[1]));
}
#define HI_MASK 0xFFFFE000u
__device__ __forceinline__ void split_tf32(float x, uint32_t& hi, uint32_t& lo) {
    uint32_t xb = __float_as_uint(x);
    hi = xb & HI_MASK;
    float lof = x - __uint_as_float(hi);
    lo = __float_as_uint(lof) & HI_MASK;
}

// ================= covariance GEMM (symmetric, upper-tri tiles only) =================
// cov[i,j] = (sum_k x[i,k] x[j,k]) / M - mean_i * mean_j, via 3xTF32 mma.sync.
#define KCH  32
#define GT   256
#define APAD 36
#define ATILE_F (128*APAD)
#define STAGE_F (2*ATILE_F)
#define GEMM_SMEM (2*STAGE_F*4)   // 73728 bytes

__constant__ int c_bi[10] = {0,0,0,0,1,1,1,2,2,3};
__constant__ int c_bj[10] = {0,1,2,3,1,2,3,2,3,3};

__global__ void __launch_bounds__(GT)
cov_gemm(const float* __restrict__ xg, float* __restrict__ Cg,
         const float* __restrict__ meang)
{
    extern __shared__ float sm[];
    const int tid = threadIdx.x;
    const int b = blockIdx.z;
    const float* A  = xg + (long)b * C_ * M_;
    float*       C  = Cg + (long)b * NSQ;
    const int ib = c_bi[blockIdx.x] * 128;
    const int jb = c_bj[blockIdx.x] * 128;
    const int K = M_;
    const float covInvM = 1.0f / M_;

    const int wid = tid >> 5, lane = tid & 31;
    const int wm = wid & 1, wn = wid >> 1;
    const int gid = lane >> 2, tig = lane & 3;

    float acc[4][4][4];
    #pragma unroll
    for (int mf = 0; mf < 4; mf++)
        #pragma unroll
        for (int nf = 0; nf < 4; nf++)
            #pragma unroll
            for (int e = 0; e < 4; e++) acc[mf][nf][e] = 0.f;

    const int NC = (K + KCH - 1) / KCH;
    float4 ra[4], rb[4];

    #pragma unroll
    for (int q = 0; q < 4; q++) {
        int f = tid + q * GT; int r = f >> 3; int k = (f & 7) * 4;
        ra[q] = (k < K) ? *(const float4*)(A + (long)(ib + r) * M_ + k) : make_float4(0,0,0,0);
        rb[q] = (k < K) ? *(const float4*)(A + (long)(jb + r) * M_ + k) : make_float4(0,0,0,0);
    }
    #pragma unroll
    for (int q = 0; q < 4; q++) {
        int f = tid + q * GT; int r = f >> 3; int c = (f & 7) * 4;
        *(float4*)(sm + (long)r * APAD + c)           = ra[q];
        *(float4*)(sm + ATILE_F + (long)r * APAD + c) = rb[q];
    }
    __syncthreads();

    for (int i = 0; i < NC; i++) {
        if (i + 1 < NC) {
            const int k0 = (i + 1) * KCH;
            #pragma unroll
            for (int q = 0; q < 4; q++) {
                int f = tid + q * GT; int r = f >> 3; int k = k0 + (f & 7) * 4;
                ra[q] = (k < K) ? *(const float4*)(A + (long)(ib + r) * M_ + k) : make_float4(0,0,0,0);
                rb[q] = (k < K) ? *(const float4*)(A + (long)(jb + r) * M_ + k) : make_float4(0,0,0,0);
            }
        }
        const float* As = sm + (i & 1) * STAGE_F;
        const float* Bs = As + ATILE_F;
        #pragma unroll
        for (int ks = 0; ks < 4; ks++) {
            uint32_t ah[4][4], al[4][4];
            #pragma unroll
            for (int mf = 0; mf < 4; mf++) {
                int base = (wm * 64 + mf * 16 + gid) * APAD + ks * 8 + tig;
                split_tf32(As[base],                ah[mf][0], al[mf][0]);
                split_tf32(As[base + 8 * APAD],     ah[mf][1], al[mf][1]);
                split_tf32(As[base + 4],            ah[mf][2], al[mf][2]);
                split_tf32(As[base + 8 * APAD + 4], ah[mf][3], al[mf][3]);
            }
            uint32_t bh[4][2], bl[4][2];
            #pragma unroll
            for (int nf = 0; nf < 4; nf++) {
                int base = (wn * 32 + nf * 8 + gid) * APAD + ks * 8 + tig;
                split_tf32(Bs[base],     bh[nf][0], bl[nf][0]);
                split_tf32(Bs[base + 4], bh[nf][1], bl[nf][1]);
            }
            #pragma unroll
            for (int mf = 0; mf < 4; mf++)
                #pragma unroll
                for (int nf = 0; nf < 4; nf++) {
                    mma_tf32(acc[mf][nf], ah[mf], bh[nf]);
                    mma_tf32(acc[mf][nf], ah[mf], bl[nf]);
                    mma_tf32(acc[mf][nf], al[mf], bh[nf]);
                }
        }
        if (i + 1 < NC) {
            float* Ad = sm + ((i + 1) & 1) * STAGE_F;
            #pragma unroll
            for (int q = 0; q < 4; q++) {
                int f = tid + q * GT; int r = f >> 3; int c = (f & 7) * 4;
                *(float4*)(Ad + (long)r * APAD + c)           = ra[q];
                *(float4*)(Ad + ATILE_F + (long)r * APAD + c) = rb[q];
            }
        }
        __syncthreads();
    }

    // epilogue: cov value + symmetric write
    const bool offdiag = (ib != jb);
    #pragma unroll
    for (int mf = 0; mf < 4; mf++) {
        const int row0 = ib + wm * 64 + mf * 16 + gid;
        float mi0 = meang[b * C_ + row0];
        float mi1 = meang[b * C_ + row0 + 8];
        #pragma unroll
        for (int nf = 0; nf < 4; nf++) {
            const int col0 = jb + wn * 32 + nf * 8 + tig * 2;
            float mj0 = meang[b * C_ + col0], mj1 = meang[b * C_ + col0 + 1];
            float c0 = acc[mf][nf][0] * covInvM - mi0 * mj0;
            float c1 = acc[mf][nf][1] * covInvM - mi0 * mj1;
            float c2 = acc[mf][nf][2] * covInvM - mi1 * mj0;
            float c3 = acc[mf][nf][3] * covInvM - mi1 * mj1;
            *(float2*)(C + (long)row0 * C_ + col0)       = make_float2(c0, c1);
            *(float2*)(C + (long)(row0 + 8) * C_ + col0) = make_float2(c2, c3);
            if (offdiag) {
                C[(long)col0 * C_ + row0]           = c0;
                C[(long)(col0 + 1) * C_ + row0]     = c1;
                C[(long)col0 * C_ + row0 + 8]       = c2;
                C[(long)(col0 + 1) * C_ + row0 + 8] = c3;
            }
        }
    }
}

// ---------------- per-row mean of x ----------------
__global__ void mean_kernel(const float* __restrict__ x, float* __restrict__ mean)
{
    int warp = (blockIdx.x * blockDim.x + threadIdx.x) >> 5;
    int lane = threadIdx.x & 31;
    if (warp >= B_*C_) return;
    const float* row = x + (long)warp * M_;
    float s = 0.f;
    for (int k = lane; k < M_; k += 32) s += row[k];
    #pragma unroll
    for (int off = 16; off; off >>= 1) s += __shfl_down_sync(0xffffffffu, s, off);
    if (lane == 0) mean[warp] = s * (1.0f / M_);
}

// ---------------- trace ----------------
__global__ void trace_kernel(const float* __restrict__ A,
                             float* __restrict__ itr, float* __restrict__ str)
{
    __shared__ float sh[512];
    const int b = blockIdx.x;
    const int i = threadIdx.x;
    sh[i] = A[(long)b * NSQ + (long)i * C_ + i];
    __syncthreads();
    for (int off = 256; off; off >>= 1) {
        if (i < off) sh[i] += sh[i + off];
        __syncthreads();
    }
    if (i == 0) { float t = sh[0]; itr[b] = 1.0f / t; str[b] = sqrtf(t); }
}

// ================= Newton-Schulz vector chain =================
// All of Y_k, Z_k, W_k are polynomials in T = A/tr (they commute; Y_k = T Z_k).
// Ysqrt/sqrt(tr) = T * W0 * W1 * W2 * W3 * W4, with W_k = 1.5I - 0.5 S_k,
// S_0 = T, S_{k+1} = S_k W_k^2. Output needs only 1^T * Ysqrt -> 122 matvecs.
struct ChainCtx {
    const float* Ab;   // batch covariance, row-major 512x512
    float* v;          // smem current vector [512]
    float* partial;    // smem [8*512]
    float* pool;       // smem save stack [5*512]
    float  inv;        // 1/trace
    int    tid;
};

// v <- v^T * T  (T = A * inv). out[j] = inv * sum_i v[i] * A[i*512+j]
__device__ void do_matvec(ChainCtx& c)
{
    const int j4 = c.tid & 127;         // column group (4 cols)
    const int isec = c.tid >> 7;        // 0..7, each covers 64 rows
    float4 acc = make_float4(0.f, 0.f, 0.f, 0.f);
    const float* base = c.Ab + (long)isec * 64 * C_ + j4 * 4;
    const float* vs = c.v + isec * 64;
    #pragma unroll 4
    for (int ii = 0; ii < 64; ii++) {
        float s = vs[ii];
        float4 t = *(const float4*)(base + (long)ii * C_);
        acc.x = fmaf(s, t.x, acc.x);
        acc.y = fmaf(s, t.y, acc.y);
        acc.z = fmaf(s, t.z, acc.z);
        acc.w = fmaf(s, t.w, acc.w);
    }
    *(float4*)(c.partial + isec * 512 + j4 * 4) = acc;
    __syncthreads();
    if (c.tid < 512) {
        float s = 0.f;
        #pragma unroll
        for (int e = 0; e < 8; e++) s += c.partial[e * 512 + c.tid];
        c.v[c.tid] = s * c.inv;
    }
    __syncthreads();
}

__device__ void applyS(int k, ChainCtx& c, int sp);

// v <- v * W_k = 1.5 v - 0.5 (v S_k)
__device__ void applyW(int k, ChainCtx& c, int sp)
{
    float* save = c.pool + sp * 512;
    if (c.tid < 512) save[c.tid] = c.v[c.tid];
    __syncthreads();
    applyS(k, c, sp + 1);
    if (c.tid < 512) c.v[c.tid] = 1.5f * save[c.tid] - 0.5f * c.v[c.tid];
    __syncthreads();
}

// v <- v * S_k ; S_0 = T, S_k = S_{k-1} W_{k-1} W_{k-1}
__device__ void applyS(int k, ChainCtx& c, int sp)
{
    if (k == 0) { do_matvec(c); return; }
    applyS(k - 1, c, sp);
    applyW(k - 1, c, sp);
    applyW(k - 1, c, sp);
}

__global__ void __launch_bounds__(1024)
chain_kernel(const float* __restrict__ A, const float* __restrict__ itr,
             const float* __restrict__ str, float* __restrict__ cs)
{
    __shared__ float v[512];
    __shared__ float partial[8 * 512];
    __shared__ float pool[5 * 512];
    const int b = blockIdx.x;
    const int tid = threadIdx.x;

    ChainCtx c;
    c.Ab = A + (long)b * NSQ;
    c.v = v; c.partial = partial; c.pool = pool;
    c.inv = itr[b]; c.tid = tid;

    if (tid < 512) v[tid] = 1.0f;
    __syncthreads();

    do_matvec(c);                 // u = 1^T * T   (Y_0 = T)
    for (int k = 0; k < 5; k++)   // u = u * W_k   (k=4 is the final half-step)
        applyW(k, c, 0);

    if (tid < 512) cs[b * C_ + tid] = v[tid] * str[b] * (1.0f / C_);
}

// ---------------- out = cov_sum * x ----------------
__global__ void scale_kernel(const float* __restrict__ x,
                             const float* __restrict__ cs, float* __restrict__ out)
{
    long i4 = (long)blockIdx.x * blockDim.x + threadIdx.x;
    const long total4 = (long)B_ * C_ * M_ / 4;
    if (i4 >= total4) return;
    long e = i4 * 4;
    int bc = (int)(e / M_);
    float s = cs[bc];
    float4 v = *(const float4*)(x + e);
    v.x *= s; v.y *= s; v.z *= s; v.w *= s;
    *(float4*)(out + e) = v;
}

// ---------------- launcher ----------------
extern "C" void kernel_launch(void* const* d_in, const int* in_sizes, int n_in,
                              void* d_out, int out_size)
{
    const float* x = (const float*)d_in[0];
    float* out = (float*)d_out;

    float *A, *mean, *itr, *str, *cs;
    cudaGetSymbolAddress((void**)&A,    g_A);
    cudaGetSymbolAddress((void**)&mean, g_mean);
    cudaGetSymbolAddress((void**)&itr,  g_itr);
    cudaGetSymbolAddress((void**)&str,  g_str);
    cudaGetSymbolAddress((void**)&cs,   g_cs);

    cudaFuncSetAttribute(cov_gemm, cudaFuncAttributeMaxDynamicSharedMemorySize, GEMM_SMEM);

    // 1) row means
    mean_kernel<<<(B_*C_ + 7) / 8, 256>>>(x, mean);

    // 2) covariance (symmetric: 10 upper-tri tiles, write both halves)
    cov_gemm<<<dim3(10, 1, B_), GT, GEMM_SMEM>>>(x, A, mean);

    // 3) trace scalars
    trace_kernel<<<B_, 512>>>(A, itr, str);

    // 4) Newton-Schulz collapsed to 122 matvecs per batch
    chain_kernel<<<B_, 1024>>>(A, itr, str, cs);

    // 5) out = cov_sum[b][c] * x
    const long total4 = (long)B_ * C_ * M_ / 4;
    scale_kernel<<<(int)((total4 + 255) / 256), 256>>>(x, cs, out);

    (void)in_sizes; (void)n_in; (void)out_size;
}